// round 6
// baseline (speedup 1.0000x reference)
#include <cuda_runtime.h>
#include <cuda_fp16.h>
#include <cstdint>

#define NUM_CODES 100000
#define DIM 64
#define NVISITS 65536
#define LCODES 48

// fp16 pre-scaled tangent table + trailing ZERO row (index NUM_CODES) for
// masked slots. Row = 64 halfs = 128 B = one L2 line. ~12.8 MB, L2-resident.
__device__ __align__(16) __half2 g_tang[(size_t)(NUM_CODES + 1) * (DIM / 2)];

// ---------------------------------------------------------------------------
// Pass 1: tang[c] = (atanh(min(||emb_c||,1-1e-7)) / max(||emb_c||,1e-15)) * emb_c
// One warp per row; lane owns 2 dims. Butterfly norm reduce, Taylor atanh(x)/x
// in the small-norm regime (data: ||x|| ~ 0.008). Warp NUM_CODES zeroes pad row.
// ---------------------------------------------------------------------------
__global__ void __launch_bounds__(256) build_tangents(const float* __restrict__ emb) {
    int warp = (blockIdx.x * blockDim.x + threadIdx.x) >> 5;
    int lane = threadIdx.x & 31;
    if (warp > NUM_CODES) return;

    if (warp == NUM_CODES) {
        g_tang[(size_t)warp * (DIM / 2) + lane] = __half2half2(__ushort_as_half(0));
        return;
    }

    const float2 v = reinterpret_cast<const float2*>(emb + (size_t)warp * DIM)[lane];
    float ss = v.x * v.x + v.y * v.y;
    #pragma unroll
    for (int o = 16; o; o >>= 1)
        ss += __shfl_xor_sync(0xffffffffu, ss, o);

    float s;
    if (ss < 0.09f) {
        // atanh(x)/x = 1 + y/3 + y^2/5 + y^3/7 + y^4/9, y = x^2 = ss.
        s = 1.0f + ss * (0.33333334f + ss * (0.2f + ss * (0.14285715f + ss * 0.11111111f)));
    } else {
        float n = fmaxf(sqrtf(ss), 1e-15f);
        float a = fminf(n, 1.0f - 1e-7f);
        s = atanhf(a) / n;
    }

    g_tang[(size_t)warp * (DIM / 2) + lane] =
        __float22half2_rn(make_float2(s * v.x, s * v.y));
}

// half2 add on raw u32 payloads (HADD2).
__device__ __forceinline__ uint32_t hadd2u(uint32_t a, uint32_t b) {
    uint32_t r;
    asm("add.rn.f16x2 %0, %1, %2;" : "=r"(r) : "r"(a), "r"(b));
    return r;
}

// Convert one half2 to f32x2 and add into a packed f32x2 accumulator.
__device__ __forceinline__ void hacc2(uint32_t h2, unsigned long long& acc) {
    asm("{\n\t"
        ".reg .f16 l, h;\n\t"
        ".reg .f32 fl, fh;\n\t"
        ".reg .b64 fv;\n\t"
        "mov.b32 {l, h}, %1;\n\t"
        "cvt.f32.f16 fl, l;\n\t"
        "cvt.f32.f16 fh, h;\n\t"
        "mov.b64 fv, {fl, fh};\n\t"
        "add.rn.f32x2 %0, %0, fv;\n\t"
        "}" : "+l"(acc) : "r"(h2));
}

__device__ __forceinline__ void fadd2(float& x, float& y, float ox, float oy) {
    unsigned long long a, b;
    asm("mov.b64 %0, {%1, %2};" : "=l"(a) : "f"(x), "f"(y));
    asm("mov.b64 %0, {%1, %2};" : "=l"(b) : "f"(ox), "f"(oy));
    asm("add.rn.f32x2 %0, %0, %1;" : "+l"(a) : "l"(b));
    asm("mov.b64 {%0, %1}, %2;" : "=f"(x), "=f"(y) : "l"(a));
}

// 16B streaming (L2-only) load.
__device__ __forceinline__ uint4 ldg_cg(const void* p) {
    uint4 r;
    asm("ld.global.cg.v4.u32 {%0,%1,%2,%3}, [%4];"
        : "=r"(r.x), "=r"(r.y), "=r"(r.z), "=r"(r.w) : "l"(p));
    return r;
}

// ---------------------------------------------------------------------------
// Pass 2: out[visit] = mean over valid codes of tang[code].
// One warp per visit. Quarter q owns the CONTIGUOUS slot chunk [12q, 12q+12):
// its 12 ids arrive in 3 broadcast LDG.128s. Gathers: quarter-warp (8 lanes x
// 16B) per fp16 row -> one LDG.128 covers 4 rows; 12 gathers, L2-only (.cg).
// Pad ids clamp to the zero row via unsigned min (1 instr). Two-level HADD2
// tree + packed f32x2 accumulate; quarters combined with a shuffle reduce.
// ---------------------------------------------------------------------------
__global__ void __launch_bounds__(256, 5) visit_mean(const int* __restrict__ ids,
                                                     float* __restrict__ out) {
    int warp = (blockIdx.x * blockDim.x + threadIdx.x) >> 5;
    int lane = threadIdx.x & 31;
    if (warp >= NVISITS) return;

    const int quarter = lane >> 3;   // owns slots [12*quarter, 12*quarter+12)
    const int ql      = lane & 7;    // 16B chunk within row: dims [8ql, 8ql+8)

    // 12 ids per quarter in 3 uint4 loads (broadcast within the quarter).
    const uint4* __restrict__ vid4 = reinterpret_cast<const uint4*>(
        ids + (size_t)warp * LCODES + 12 * quarter);
    const uint4 id0 = __ldg(vid4 + 0);
    const uint4 id1 = __ldg(vid4 + 1);
    const uint4 id2 = __ldg(vid4 + 2);

    const char* __restrict__ base = reinterpret_cast<const char*>(g_tang) + ql * 16;

    unsigned long long acc[4] = {0ull, 0ull, 0ull, 0ull};
    int cnt = 0;

    const uint4 idv[3] = {id0, id1, id2};
    #pragma unroll
    for (int g = 0; g < 3; g++) {
        const int i0 = (int)idv[g].x, i1 = (int)idv[g].y,
                  i2 = (int)idv[g].z, i3 = (int)idv[g].w;
        cnt += (i0 >= 0) + (i1 >= 0) + (i2 >= 0) + (i3 >= 0);

        // pad (-1) -> 0xFFFFFFFF -> clamps to zero row NUM_CODES (IMNMX).
        const unsigned c0 = min((unsigned)i0, (unsigned)NUM_CODES);
        const unsigned c1 = min((unsigned)i1, (unsigned)NUM_CODES);
        const unsigned c2 = min((unsigned)i2, (unsigned)NUM_CODES);
        const unsigned c3 = min((unsigned)i3, (unsigned)NUM_CODES);

        const uint4 a = ldg_cg(base + (size_t)c0 * 128u);
        const uint4 b = ldg_cg(base + (size_t)c1 * 128u);
        const uint4 c = ldg_cg(base + (size_t)c2 * 128u);
        const uint4 d = ldg_cg(base + (size_t)c3 * 128u);

        hacc2(hadd2u(hadd2u(a.x, b.x), hadd2u(c.x, d.x)), acc[0]);
        hacc2(hadd2u(hadd2u(a.y, b.y), hadd2u(c.y, d.y)), acc[1]);
        hacc2(hadd2u(hadd2u(a.z, b.z), hadd2u(c.z, d.z)), acc[2]);
        hacc2(hadd2u(hadd2u(a.w, b.w), hadd2u(c.w, d.w)), acc[3]);
    }

    float f[8];
    #pragma unroll
    for (int j = 0; j < 4; j++) {
        f[2 * j]     = __uint_as_float((unsigned)(acc[j] & 0xffffffffull));
        f[2 * j + 1] = __uint_as_float((unsigned)(acc[j] >> 32));
    }
    float fc = (float)cnt;   // per-quarter count (identical across its 8 lanes)

    // Combine the four quarter-warp accumulators (+ count) with packed adds.
    #pragma unroll
    for (int o = 16; o >= 8; o >>= 1) {
        float g[8];
        #pragma unroll
        for (int i = 0; i < 8; i++)
            g[i] = __shfl_down_sync(0xffffffffu, f[i], o);
        float gc = __shfl_down_sync(0xffffffffu, fc, o);
        #pragma unroll
        for (int j = 0; j < 4; j++)
            fadd2(f[2 * j], f[2 * j + 1], g[2 * j], g[2 * j + 1]);
        fc += gc;
    }

    if (quarter == 0) {
        float inv = 1.0f / fmaxf(fc, 1.0f);
        float4 o0 = make_float4(f[0] * inv, f[1] * inv, f[2] * inv, f[3] * inv);
        float4 o1 = make_float4(f[4] * inv, f[5] * inv, f[6] * inv, f[7] * inv);
        float4* op = reinterpret_cast<float4*>(out + (size_t)warp * DIM + ql * 8);
        op[0] = o0;
        op[1] = o1;
    }
}

extern "C" void kernel_launch(void* const* d_in, const int* in_sizes, int n_in,
                              void* d_out, int out_size) {
    const int*   code_ids = (const int*)d_in[0];   // [N, L] int32, -1 = pad
    const float* emb      = (const float*)d_in[1]; // [NUM_CODES, DIM] fp32
    float*       out      = (float*)d_out;         // [N, DIM] fp32

    (void)in_sizes; (void)n_in; (void)out_size;

    build_tangents<<<(NUM_CODES + 1 + 7) / 8, 256>>>(emb);
    visit_mean<<<NVISITS / 8, 256>>>(code_ids, out);
}

// round 7
// speedup vs baseline: 4.2108x; 4.2108x over previous
#include <cuda_runtime.h>
#include <cuda_fp16.h>
#include <cstdint>

#define NUM_CODES 100000
#define DIM 64
#define NVISITS 65536
#define LCODES 48

// fp16 pre-scaled tangent table. Row = 64 halfs = 128 B = one L2 line.
// ~12.8 MB, L2-resident.
__device__ __align__(16) __half2 g_tang[(size_t)NUM_CODES * (DIM / 2)];

// ---------------------------------------------------------------------------
// Pass 1: tang[c] = (atanh(min(||emb_c||,1-1e-7)) / max(||emb_c||,1e-15)) * emb_c
// One warp per row; lane owns 2 dims. Butterfly norm reduce, Taylor atanh(x)/x
// in the small-norm regime (data: ||x|| ~ 0.008).
// ---------------------------------------------------------------------------
__global__ void __launch_bounds__(256) build_tangents(const float* __restrict__ emb) {
    int warp = (blockIdx.x * blockDim.x + threadIdx.x) >> 5;
    int lane = threadIdx.x & 31;
    if (warp >= NUM_CODES) return;

    const float2 v = reinterpret_cast<const float2*>(emb + (size_t)warp * DIM)[lane];
    float ss = v.x * v.x + v.y * v.y;
    #pragma unroll
    for (int o = 16; o; o >>= 1)
        ss += __shfl_xor_sync(0xffffffffu, ss, o);

    float s;
    if (ss < 0.09f) {
        // atanh(x)/x = 1 + y/3 + y^2/5 + y^3/7 + y^4/9, y = x^2 = ss.
        s = 1.0f + ss * (0.33333334f + ss * (0.2f + ss * (0.14285715f + ss * 0.11111111f)));
    } else {
        float n = fmaxf(sqrtf(ss), 1e-15f);
        float a = fminf(n, 1.0f - 1e-7f);
        s = atanhf(a) / n;
    }

    g_tang[(size_t)warp * (DIM / 2) + lane] =
        __float22half2_rn(make_float2(s * v.x, s * v.y));
}

// half2 add on raw u32 payloads (HADD2).
__device__ __forceinline__ uint32_t hadd2u(uint32_t a, uint32_t b) {
    uint32_t r;
    asm("add.rn.f16x2 %0, %1, %2;" : "=r"(r) : "r"(a), "r"(b));
    return r;
}

// Convert one half2 to f32x2 and add into a packed f32x2 accumulator.
__device__ __forceinline__ void hacc2(uint32_t h2, unsigned long long& acc) {
    asm("{\n\t"
        ".reg .f16 l, h;\n\t"
        ".reg .f32 fl, fh;\n\t"
        ".reg .b64 fv;\n\t"
        "mov.b32 {l, h}, %1;\n\t"
        "cvt.f32.f16 fl, l;\n\t"
        "cvt.f32.f16 fh, h;\n\t"
        "mov.b64 fv, {fl, fh};\n\t"
        "add.rn.f32x2 %0, %0, fv;\n\t"
        "}" : "+l"(acc) : "r"(h2));
}

__device__ __forceinline__ void fadd2(float& x, float& y, float ox, float oy) {
    unsigned long long a, b;
    asm("mov.b64 %0, {%1, %2};" : "=l"(a) : "f"(x), "f"(y));
    asm("mov.b64 %0, {%1, %2};" : "=l"(b) : "f"(ox), "f"(oy));
    asm("add.rn.f32x2 %0, %0, %1;" : "+l"(a) : "l"(b));
    asm("mov.b64 {%0, %1}, %2;" : "=f"(x), "=f"(y) : "l"(a));
}

// Predicated 16B gather: returns zeros when pred is false, no memory traffic.
__device__ __forceinline__ uint4 gather_pred(bool pred, const char* p) {
    uint4 r = make_uint4(0u, 0u, 0u, 0u);
    if (pred) r = *reinterpret_cast<const uint4*>(p);
    return r;
}

// ---------------------------------------------------------------------------
// Pass 2: out[visit] = mean over valid codes of tang[code].
// One warp per visit. Quarter q owns the CONTIGUOUS slot chunk [12q, 12q+12):
// its 12 ids arrive in 3 broadcast LDG.128s (no SHFL.IDX anywhere). Gathers:
// quarter-warp (8 lanes x 16B) per fp16 row -> one LDG.128 covers 4 rows.
// Pad slots use PREDICATED loads (zero-filled, no wavefronts) -- ~30% of all
// gather traffic disappears vs the zero-row scheme. Two-level HADD2 tree +
// packed f32x2 accumulate; quarters combined with a shuffle reduce.
// ---------------------------------------------------------------------------
__global__ void __launch_bounds__(256, 6) visit_mean(const int* __restrict__ ids,
                                                     float* __restrict__ out) {
    int warp = (blockIdx.x * blockDim.x + threadIdx.x) >> 5;
    int lane = threadIdx.x & 31;
    if (warp >= NVISITS) return;

    const int quarter = lane >> 3;   // owns slots [12*quarter, 12*quarter+12)
    const int ql      = lane & 7;    // 16B chunk within row: dims [8ql, 8ql+8)

    // 12 ids per quarter in 3 uint4 loads (broadcast within the quarter).
    const uint4* __restrict__ vid4 = reinterpret_cast<const uint4*>(
        ids + (size_t)warp * LCODES + 12 * quarter);
    const uint4 id0 = __ldg(vid4 + 0);
    const uint4 id1 = __ldg(vid4 + 1);
    const uint4 id2 = __ldg(vid4 + 2);

    const char* __restrict__ base = reinterpret_cast<const char*>(g_tang) + ql * 16;

    unsigned long long acc[4] = {0ull, 0ull, 0ull, 0ull};
    int cnt = 0;

    const uint4 idv[3] = {id0, id1, id2};
    #pragma unroll
    for (int g = 0; g < 3; g++) {
        const int i0 = (int)idv[g].x, i1 = (int)idv[g].y,
                  i2 = (int)idv[g].z, i3 = (int)idv[g].w;
        cnt += (i0 >= 0) + (i1 >= 0) + (i2 >= 0) + (i3 >= 0);

        const uint4 a = gather_pred(i0 >= 0, base + (size_t)(unsigned)i0 * 128u);
        const uint4 b = gather_pred(i1 >= 0, base + (size_t)(unsigned)i1 * 128u);
        const uint4 c = gather_pred(i2 >= 0, base + (size_t)(unsigned)i2 * 128u);
        const uint4 d = gather_pred(i3 >= 0, base + (size_t)(unsigned)i3 * 128u);

        hacc2(hadd2u(hadd2u(a.x, b.x), hadd2u(c.x, d.x)), acc[0]);
        hacc2(hadd2u(hadd2u(a.y, b.y), hadd2u(c.y, d.y)), acc[1]);
        hacc2(hadd2u(hadd2u(a.z, b.z), hadd2u(c.z, d.z)), acc[2]);
        hacc2(hadd2u(hadd2u(a.w, b.w), hadd2u(c.w, d.w)), acc[3]);
    }

    float f[8];
    #pragma unroll
    for (int j = 0; j < 4; j++) {
        f[2 * j]     = __uint_as_float((unsigned)(acc[j] & 0xffffffffull));
        f[2 * j + 1] = __uint_as_float((unsigned)(acc[j] >> 32));
    }
    float fc = (float)cnt;   // per-quarter count (identical across its 8 lanes)

    // Combine the four quarter-warp accumulators (+ count) with packed adds.
    #pragma unroll
    for (int o = 16; o >= 8; o >>= 1) {
        float g[8];
        #pragma unroll
        for (int i = 0; i < 8; i++)
            g[i] = __shfl_down_sync(0xffffffffu, f[i], o);
        float gc = __shfl_down_sync(0xffffffffu, fc, o);
        #pragma unroll
        for (int j = 0; j < 4; j++)
            fadd2(f[2 * j], f[2 * j + 1], g[2 * j], g[2 * j + 1]);
        fc += gc;
    }

    if (quarter == 0) {
        float inv = 1.0f / fmaxf(fc, 1.0f);
        float4 o0 = make_float4(f[0] * inv, f[1] * inv, f[2] * inv, f[3] * inv);
        float4 o1 = make_float4(f[4] * inv, f[5] * inv, f[6] * inv, f[7] * inv);
        float4* op = reinterpret_cast<float4*>(out + (size_t)warp * DIM + ql * 8);
        op[0] = o0;
        op[1] = o1;
    }
}

extern "C" void kernel_launch(void* const* d_in, const int* in_sizes, int n_in,
                              void* d_out, int out_size) {
    const int*   code_ids = (const int*)d_in[0];   // [N, L] int32, -1 = pad
    const float* emb      = (const float*)d_in[1]; // [NUM_CODES, DIM] fp32
    float*       out      = (float*)d_out;         // [N, DIM] fp32

    (void)in_sizes; (void)n_in; (void)out_size;

    build_tangents<<<(NUM_CODES + 7) / 8, 256>>>(emb);
    visit_mean<<<NVISITS / 8, 256>>>(code_ids, out);
}

// round 8
// speedup vs baseline: 4.3146x; 1.0247x over previous
#include <cuda_runtime.h>
#include <cuda_fp16.h>
#include <cstdint>

#define NUM_CODES 100000
#define DIM 64
#define NVISITS 65536
#define LCODES 48

// fp16 pre-scaled tangent table. Row = 64 halfs = 128 B = one L2 line.
// ~12.8 MB, L2-resident.
__device__ __align__(16) __half2 g_tang[(size_t)NUM_CODES * (DIM / 2)];

// ---------------------------------------------------------------------------
// Pass 1: tang[c] = (atanh(min(||emb_c||,1-1e-7)) / max(||emb_c||,1e-15)) * emb_c
// One warp per row; lane owns 2 dims. Butterfly norm reduce, Taylor atanh(x)/x
// in the small-norm regime (data: ||x|| ~ 0.008).
// ---------------------------------------------------------------------------
__global__ void __launch_bounds__(256) build_tangents(const float* __restrict__ emb) {
    int warp = (blockIdx.x * blockDim.x + threadIdx.x) >> 5;
    int lane = threadIdx.x & 31;
    if (warp >= NUM_CODES) return;

    const float2 v = reinterpret_cast<const float2*>(emb + (size_t)warp * DIM)[lane];
    float ss = v.x * v.x + v.y * v.y;
    #pragma unroll
    for (int o = 16; o; o >>= 1)
        ss += __shfl_xor_sync(0xffffffffu, ss, o);

    float s;
    if (ss < 0.09f) {
        // atanh(x)/x = 1 + y/3 + y^2/5 + y^3/7 + y^4/9, y = x^2 = ss.
        s = 1.0f + ss * (0.33333334f + ss * (0.2f + ss * (0.14285715f + ss * 0.11111111f)));
    } else {
        float n = fmaxf(sqrtf(ss), 1e-15f);
        float a = fminf(n, 1.0f - 1e-7f);
        s = atanhf(a) / n;
    }

    g_tang[(size_t)warp * (DIM / 2) + lane] =
        __float22half2_rn(make_float2(s * v.x, s * v.y));
}

// half2 add on raw u32 payloads (HADD2).
__device__ __forceinline__ uint32_t hadd2u(uint32_t a, uint32_t b) {
    uint32_t r;
    asm("add.rn.f16x2 %0, %1, %2;" : "=r"(r) : "r"(a), "r"(b));
    return r;
}

// Convert one half2 to f32x2 and add into a packed f32x2 accumulator.
__device__ __forceinline__ void hacc2(uint32_t h2, unsigned long long& acc) {
    asm("{\n\t"
        ".reg .f16 l, h;\n\t"
        ".reg .f32 fl, fh;\n\t"
        ".reg .b64 fv;\n\t"
        "mov.b32 {l, h}, %1;\n\t"
        "cvt.f32.f16 fl, l;\n\t"
        "cvt.f32.f16 fh, h;\n\t"
        "mov.b64 fv, {fl, fh};\n\t"
        "add.rn.f32x2 %0, %0, fv;\n\t"
        "}" : "+l"(acc) : "r"(h2));
}

// Predicated 16B gather: returns zeros when pred is false, no memory traffic.
__device__ __forceinline__ uint4 gather_pred(bool pred, const char* p) {
    uint4 r = make_uint4(0u, 0u, 0u, 0u);
    if (pred) r = *reinterpret_cast<const uint4*>(p);
    return r;
}

// ---------------------------------------------------------------------------
// Pass 2: out[visit] = mean over valid codes of tang[code].
// QUARTER-WARP PER VISIT: each 8-lane quarter owns one visit end-to-end
// (no cross-quarter shuffle reduce, no tail). A warp-wide LDG.128 still
// fetches 4 independent table rows (one per quarter's visit). 12 groups:
// broadcast uint4 id load + 4 predicated gathers + two-level HADD2 tree +
// packed f32x2 accumulate. Each quarter stores its own 256B output row.
// ---------------------------------------------------------------------------
__global__ void __launch_bounds__(256, 5) visit_mean(const int* __restrict__ ids,
                                                     float* __restrict__ out) {
    int warp  = (blockIdx.x * blockDim.x + threadIdx.x) >> 5;
    int lane  = threadIdx.x & 31;
    const int quarter = lane >> 3;
    const int ql      = lane & 7;          // 16B chunk within row: dims [8ql, 8ql+8)

    const int visit = warp * 4 + quarter;  // grid sized so this never overflows

    // 48 ids of this quarter's visit: 12 broadcast uint4 loads.
    const uint4* __restrict__ vid4 =
        reinterpret_cast<const uint4*>(ids + (size_t)visit * LCODES);

    const char* __restrict__ base = reinterpret_cast<const char*>(g_tang) + ql * 16;

    unsigned long long acc[4] = {0ull, 0ull, 0ull, 0ull};
    int cnt = 0;

    #pragma unroll
    for (int g = 0; g < 12; g++) {
        const uint4 idv = __ldg(vid4 + g);
        const int i0 = (int)idv.x, i1 = (int)idv.y, i2 = (int)idv.z, i3 = (int)idv.w;
        cnt += (i0 >= 0) + (i1 >= 0) + (i2 >= 0) + (i3 >= 0);

        const uint4 a = gather_pred(i0 >= 0, base + (size_t)(unsigned)i0 * 128u);
        const uint4 b = gather_pred(i1 >= 0, base + (size_t)(unsigned)i1 * 128u);
        const uint4 c = gather_pred(i2 >= 0, base + (size_t)(unsigned)i2 * 128u);
        const uint4 d = gather_pred(i3 >= 0, base + (size_t)(unsigned)i3 * 128u);

        hacc2(hadd2u(hadd2u(a.x, b.x), hadd2u(c.x, d.x)), acc[0]);
        hacc2(hadd2u(hadd2u(a.y, b.y), hadd2u(c.y, d.y)), acc[1]);
        hacc2(hadd2u(hadd2u(a.z, b.z), hadd2u(c.z, d.z)), acc[2]);
        hacc2(hadd2u(hadd2u(a.w, b.w), hadd2u(c.w, d.w)), acc[3]);
    }

    float f[8];
    #pragma unroll
    for (int j = 0; j < 4; j++) {
        f[2 * j]     = __uint_as_float((unsigned)(acc[j] & 0xffffffffull));
        f[2 * j + 1] = __uint_as_float((unsigned)(acc[j] >> 32));
    }

    const float inv = 1.0f / fmaxf((float)cnt, 1.0f);
    float4 o0 = make_float4(f[0] * inv, f[1] * inv, f[2] * inv, f[3] * inv);
    float4 o1 = make_float4(f[4] * inv, f[5] * inv, f[6] * inv, f[7] * inv);
    float4* op = reinterpret_cast<float4*>(out + (size_t)visit * DIM + ql * 8);
    op[0] = o0;
    op[1] = o1;
}

extern "C" void kernel_launch(void* const* d_in, const int* in_sizes, int n_in,
                              void* d_out, int out_size) {
    const int*   code_ids = (const int*)d_in[0];   // [N, L] int32, -1 = pad
    const float* emb      = (const float*)d_in[1]; // [NUM_CODES, DIM] fp32
    float*       out      = (float*)d_out;         // [N, DIM] fp32

    (void)in_sizes; (void)n_in; (void)out_size;

    build_tangents<<<(NUM_CODES + 7) / 8, 256>>>(emb);
    // 32 visits per 256-thread block: 65536 / 32 = 2048 blocks.
    visit_mean<<<NVISITS / 32, 256>>>(code_ids, out);
}